// round 16
// baseline (speedup 1.0000x reference)
#include <cuda_runtime.h>
#include <cuda_fp16.h>
#include <math.h>

// ---------------------------------------------------------------------------
// N=100000, F_in=128, F_hid=64, F_out=40, E=1600000 (+N self loops).
// h1 / h2 stored fp16; fp32 accumulation everywhere.
// CSR chain: memset(cnt)+memset(bar) -> hist(x4 vectorized, inline dtype
// detect) -> scan (writes self loops) -> fill (x4 vectorized, edges only).
// ---------------------------------------------------------------------------
#define MAXN 100000
#define MAXE 1700096

__device__ __half g_h1h[(size_t)MAXN * 64];
__device__ float  g_h1r[(size_t)MAXN * 64];
__device__ __half g_h2h[(size_t)MAXN * 40];
__device__ float  g_as[MAXN];
__device__ float  g_ad[MAXN];
__device__ int    g_cnt[MAXN];
__device__ int    g_off[MAXN + 1];
__device__ int    g_srcs[MAXE];
__device__ int    g_rank[MAXE];
__device__ int    g_partials[128];
__device__ int    g_barrier;

// Inline dtype detection: for int64 (little-endian) every odd 32-bit word of
// values < 2^31 is zero; 32 consecutive zero odd-words from random int32
// indices is impossible.
static __device__ __forceinline__ int detect_is64(const unsigned int* w) {
    unsigned int any = 0;
    #pragma unroll
    for (int k = 0; k < 32; k++) any |= w[2 * k + 1];
    return any == 0u;
}

// ---------------------------------------------------------------------------
// Hist: 4 edges per thread; count destinations, record per-edge rank.
// ---------------------------------------------------------------------------
__global__ void hist_kernel(const unsigned int* __restrict__ w,
                            int* __restrict__ cnt, int* __restrict__ rank,
                            long long E) {
    __shared__ int sis64;
    if (threadIdx.x == 0) sis64 = detect_is64(w);
    __syncthreads();
    int is64 = sis64;

    long long i4 = ((long long)blockIdx.x * blockDim.x + threadIdx.x) * 4;
    if (i4 >= E) return;
    int nv = (int)((E - i4 < 4) ? (E - i4) : 4);

    int d[4];
    if (is64) {
        const uint2* w2 = (const uint2*)w;
        #pragma unroll
        for (int q = 0; q < 4; q++)
            if (q < nv) d[q] = (int)w2[E + i4 + q].x;
    } else {
        if (nv == 4 && (((E + i4) & 3) == 0)) {
            uint4 v = *(const uint4*)&w[E + i4];
            d[0] = (int)v.x; d[1] = (int)v.y; d[2] = (int)v.z; d[3] = (int)v.w;
        } else {
            #pragma unroll
            for (int q = 0; q < 4; q++)
                if (q < nv) d[q] = (int)w[E + i4 + q];
        }
    }
    int r[4];
    #pragma unroll
    for (int q = 0; q < 4; q++)
        if (q < nv) r[q] = atomicAdd(&cnt[d[q]], 1);
    if (nv == 4) *(int4*)&rank[i4] = make_int4(r[0], r[1], r[2], r[3]);
    else {
        #pragma unroll
        for (int q = 0; q < 4; q++)
            if (q < nv) rank[i4 + q] = r[q];
    }
}

// ---------------------------------------------------------------------------
// One-kernel exclusive scan of (cnt[i]+1) -> off; also places self loops
// (srcs[off[i] + cnt[i]] = i).  Barrier counter memset to 0 pre-launch.
// ---------------------------------------------------------------------------
__global__ void scan_kernel(const int* __restrict__ cnt,
                            int* __restrict__ off, int* __restrict__ srcs,
                            int* __restrict__ partials, int* __restrict__ barrier,
                            int n, int total) {
    __shared__ int sm[1024];
    __shared__ int pf[128];
    int tid = threadIdx.x, b = blockIdx.x;
    int i = b * 1024 + tid;
    int cv = (i < n) ? cnt[i] : 0;
    int v = (i < n) ? cv + 1 : 0;   // +1 = self loop
    sm[tid] = v;
    __syncthreads();
    #pragma unroll
    for (int o = 1; o < 1024; o <<= 1) {
        int t = (tid >= o) ? sm[tid - o] : 0;
        __syncthreads();
        sm[tid] += t;
        __syncthreads();
    }
    int incl = sm[tid];

    if (tid == 0) {
        partials[b] = sm[1023];
        __threadfence();
        atomicAdd(barrier, 1);
        while (atomicAdd(barrier, 0) < gridDim.x) {}
    }
    __syncthreads();

    pf[tid & 127] = 0;
    __syncthreads();
    if (tid < 128) pf[tid] = (tid < b) ? partials[tid] : 0;
    __syncthreads();
    #pragma unroll
    for (int o = 64; o; o >>= 1) {
        if (tid < o) pf[tid] += pf[tid + o];
        __syncthreads();
    }
    int prefix = pf[0];

    if (i < n) {
        int o = prefix + incl - v;
        off[i] = o;
        srcs[o + cv] = i;   // self loop placed after the cv real edges
    }
    if (i == 0) off[n] = total;
}

// ---------------------------------------------------------------------------
// Fill: 4 edges per thread, atomic-free scatter via precomputed ranks.
// ---------------------------------------------------------------------------
__global__ void fill_kernel(const unsigned int* __restrict__ w,
                            const int* __restrict__ off,
                            const int* __restrict__ rank,
                            int* __restrict__ srcs, long long E) {
    __shared__ int sis64;
    if (threadIdx.x == 0) sis64 = detect_is64(w);
    __syncthreads();
    int is64 = sis64;

    long long i4 = ((long long)blockIdx.x * blockDim.x + threadIdx.x) * 4;
    if (i4 >= E) return;
    int nv = (int)((E - i4 < 4) ? (E - i4) : 4);

    int s[4], d[4];
    if (is64) {
        const uint2* w2 = (const uint2*)w;
        #pragma unroll
        for (int q = 0; q < 4; q++)
            if (q < nv) { s[q] = (int)w2[i4 + q].x; d[q] = (int)w2[E + i4 + q].x; }
    } else {
        if (nv == 4 && (((E + i4) & 3) == 0)) {
            uint4 vs = *(const uint4*)&w[i4];
            uint4 vd = *(const uint4*)&w[E + i4];
            s[0] = (int)vs.x; s[1] = (int)vs.y; s[2] = (int)vs.z; s[3] = (int)vs.w;
            d[0] = (int)vd.x; d[1] = (int)vd.y; d[2] = (int)vd.z; d[3] = (int)vd.w;
        } else {
            #pragma unroll
            for (int q = 0; q < 4; q++)
                if (q < nv) { s[q] = (int)w[i4 + q]; d[q] = (int)w[E + i4 + q]; }
        }
    }
    int r[4];
    if (nv == 4) { int4 rv = *(const int4*)&rank[i4]; r[0]=rv.x; r[1]=rv.y; r[2]=rv.z; r[3]=rv.w; }
    else {
        #pragma unroll
        for (int q = 0; q < 4; q++)
            if (q < nv) r[q] = rank[i4 + q];
    }
    #pragma unroll
    for (int q = 0; q < 4; q++)
        if (q < nv) srcs[off[d[q]] + r[q]] = s[q];
}

// ---------------------------------------------------------------------------
// GEMM1: h = x @ W (K=128, C=64), fp32 accumulation, fp16 output rows.
// Alpha dots fused into epilogue.
// ---------------------------------------------------------------------------
__global__ void gemm1_kernel(const float* __restrict__ x,
                             const float* __restrict__ W,
                             const float* __restrict__ asv,
                             const float* __restrict__ adv,
                             __half* __restrict__ h,
                             float* __restrict__ as_, float* __restrict__ ad_,
                             int Nn) {
    __shared__ float Xs[128 * 32];
    __shared__ float Ws[32 * 64];
    int tid = threadIdx.x;
    int row0 = blockIdx.x * 128;
    int rt = tid >> 3;
    int ct = tid & 7;
    int r0 = rt * 8;
    int kx = (rt & 3) << 3;

    unsigned long long acc[8][4];
    #pragma unroll
    for (int i = 0; i < 8; i++)
        #pragma unroll
        for (int j = 0; j < 4; j++) acc[i][j] = 0ull;

    const float4* x4 = (const float4*)x;

    for (int kc = 0; kc < 4; kc++) {
        const float4* W4 = (const float4*)(W + kc * 32 * 64);
        #pragma unroll
        for (int i = tid; i < 512; i += 128) ((float4*)Ws)[i] = W4[i];
        #pragma unroll
        for (int i = tid; i < 1024; i += 128) {
            int row = i >> 3;
            int c4  = i & 7;
            int gr = row0 + row;
            float4 v = (gr < Nn) ? x4[(size_t)gr * 32 + kc * 8 + c4]
                                 : make_float4(0.f, 0.f, 0.f, 0.f);
            int col = (c4 * 4) ^ (((row >> 3) & 3) << 3);
            *(float4*)&Xs[row * 32 + col] = v;
        }
        __syncthreads();

        #pragma unroll
        for (int k = 0; k < 32; k++) {
            longlong2 w0 = *(const longlong2*)&Ws[k * 64 + ct * 8];
            longlong2 w1 = *(const longlong2*)&Ws[k * 64 + ct * 8 + 4];
            #pragma unroll
            for (int i = 0; i < 8; i++) {
                float xv = Xs[(r0 + i) * 32 + (k ^ kx)];
                unsigned long long xx;
                asm("mov.b64 %0, {%1, %1};" : "=l"(xx) : "r"(__float_as_uint(xv)));
                asm("fma.rn.f32x2 %0, %1, %2, %0;" : "+l"(acc[i][0]) : "l"(xx), "l"((unsigned long long)w0.x));
                asm("fma.rn.f32x2 %0, %1, %2, %0;" : "+l"(acc[i][1]) : "l"(xx), "l"((unsigned long long)w0.y));
                asm("fma.rn.f32x2 %0, %1, %2, %0;" : "+l"(acc[i][2]) : "l"(xx), "l"((unsigned long long)w1.x));
                asm("fma.rn.f32x2 %0, %1, %2, %0;" : "+l"(acc[i][3]) : "l"(xx), "l"((unsigned long long)w1.y));
            }
        }
        __syncthreads();
    }

    const float4* as4 = (const float4*)asv;
    const float4* ad4 = (const float4*)adv;
    float4 sa0 = as4[ct * 2], sa1 = as4[ct * 2 + 1];
    float4 da0 = ad4[ct * 2], da1 = ad4[ct * 2 + 1];

    #pragma unroll
    for (int i = 0; i < 8; i++) {
        int row = row0 + r0 + i;
        float o[8];
        #pragma unroll
        for (int j = 0; j < 4; j++) {
            unsigned int lo, hi;
            asm("mov.b64 {%0, %1}, %2;" : "=r"(lo), "=r"(hi) : "l"(acc[i][j]));
            o[2 * j]     = __uint_as_float(lo);
            o[2 * j + 1] = __uint_as_float(hi);
        }
        float ps = o[0]*sa0.x + o[1]*sa0.y + o[2]*sa0.z + o[3]*sa0.w
                 + o[4]*sa1.x + o[5]*sa1.y + o[6]*sa1.z + o[7]*sa1.w;
        float pd = o[0]*da0.x + o[1]*da0.y + o[2]*da0.z + o[3]*da0.w
                 + o[4]*da1.x + o[5]*da1.y + o[6]*da1.z + o[7]*da1.w;
        #pragma unroll
        for (int m = 1; m < 8; m <<= 1) {
            ps += __shfl_xor_sync(0xffffffffu, ps, m);
            pd += __shfl_xor_sync(0xffffffffu, pd, m);
        }
        if (row < Nn) {
            __half2 p0 = __floats2half2_rn(o[0], o[1]);
            __half2 p1 = __floats2half2_rn(o[2], o[3]);
            __half2 p2 = __floats2half2_rn(o[4], o[5]);
            __half2 p3 = __floats2half2_rn(o[6], o[7]);
            uint4 pk;
            pk.x = *(unsigned int*)&p0; pk.y = *(unsigned int*)&p1;
            pk.z = *(unsigned int*)&p2; pk.w = *(unsigned int*)&p3;
            *(uint4*)(h + (size_t)row * 64 + ct * 8) = pk;
            if (ct == 0) { as_[row] = ps; ad_[row] = pd; }
        }
    }
}

// ---------------------------------------------------------------------------
// GEMM2: h2 = h1r @ W2 (K=64, C=40), fp16 output, alpha dots fused.
// ---------------------------------------------------------------------------
__global__ void gemm2_kernel(const float* __restrict__ x,
                             const float* __restrict__ W,
                             const float* __restrict__ asv,
                             const float* __restrict__ adv,
                             __half* __restrict__ h,
                             float* __restrict__ as_, float* __restrict__ ad_,
                             int Nn) {
    __shared__ float Xs[32][64];
    __shared__ float Ws[64][40];
    int tid = threadIdx.x;
    int row0 = blockIdx.x * 32;

    #pragma unroll
    for (int i = tid; i < 64 * 40; i += 128) Ws[i / 40][i % 40] = W[i];

    const float4* x4 = (const float4*)x;
    float4* Xs4 = (float4*)Xs;
    #pragma unroll
    for (int i = tid; i < 32 * 16; i += 128) {
        long long gi = (long long)row0 * 16 + i;
        Xs4[i] = (gi < (long long)Nn * 16) ? x4[gi] : make_float4(0.f, 0.f, 0.f, 0.f);
    }
    __syncthreads();

    int r0 = (tid >> 3) * 2;
    int c0 = (tid & 7) * 5;
    float acc[2][5] = {};
    #pragma unroll 4
    for (int k = 0; k < 64; k++) {
        float xv0 = Xs[r0][k];
        float xv1 = Xs[r0 + 1][k];
        #pragma unroll
        for (int j = 0; j < 5; j++) {
            float wv = Ws[k][c0 + j];
            acc[0][j] += xv0 * wv;
            acc[1][j] += xv1 * wv;
        }
    }

    float sa[5], da[5];
    #pragma unroll
    for (int j = 0; j < 5; j++) { sa[j] = asv[c0 + j]; da[j] = adv[c0 + j]; }

    #pragma unroll
    for (int i = 0; i < 2; i++) {
        int row = row0 + r0 + i;
        float ps = 0.f, pd = 0.f;
        #pragma unroll
        for (int j = 0; j < 5; j++) {
            ps += acc[i][j] * sa[j];
            pd += acc[i][j] * da[j];
        }
        #pragma unroll
        for (int m = 1; m < 8; m <<= 1) {
            ps += __shfl_xor_sync(0xffffffffu, ps, m);
            pd += __shfl_xor_sync(0xffffffffu, pd, m);
        }
        if (row < Nn) {
            __half* dstp = h + (size_t)row * 40 + c0;
            #pragma unroll
            for (int j = 0; j < 5; j++) dstp[j] = __float2half_rn(acc[i][j]);
            if ((tid & 7) == 0) { as_[row] = ps; ad_[row] = pd; }
        }
    }
}

// ---------------------------------------------------------------------------
// Fused GAT aggregation (unchanged from round 15 best): warp per dst, fp16
// rows, deg<=16 fast path, 8-edge chunks otherwise, rden post-combine.
// ---------------------------------------------------------------------------
template <int F, bool FINAL>
__global__ void gat_agg_kernel(const int* __restrict__ srcs,
                               const int* __restrict__ off,
                               const float* __restrict__ as_,
                               const float* __restrict__ ad_,
                               const __half* __restrict__ h,
                               const float* __restrict__ bias,
                               float* __restrict__ outp, int Nn) {
    constexpr int LROW = F / 8;
    __shared__ float exco[8][96];
    __shared__ int   sso[8][96];
    int w = threadIdx.x >> 5, lane = threadIdx.x & 31;
    int d = blockIdx.x * 8 + w;
    if (d >= Nn) return;
    int beg = off[d], end = off[d + 1];
    int deg = end - beg;
    float advv = ad_[d];
    float* exc = exco[w];
    int*   ssc = sso[w];
    bool fits = (deg <= 96);

    float sum = 0.f;
    for (int i = lane; i < deg; i += 32) {
        int s = srcs[beg + i];
        float e = as_[s] + advv;
        e = (e > 0.f) ? e : 0.2f * e;
        float xv = __expf(e);
        if (fits) { exc[i] = xv; ssc[i] = s; }
        sum += xv;
    }
    #pragma unroll
    for (int m = 16; m; m >>= 1) sum += __shfl_xor_sync(0xffffffffu, sum, m);
    float rden = 1.0f / sum;
    __syncwarp();

    int g = lane >> 3, l8 = lane & 7;
    const bool act = (F == 64) || (l8 < LROW);
    float a[8] = {0.f, 0.f, 0.f, 0.f, 0.f, 0.f, 0.f, 0.f};
    const float4* h4 = (const float4*)h;

    #define ACC8(vv, cc) { \
        const __half2* hp = (const __half2*)&(vv); \
        float2 f0 = __half22float2(hp[0]); \
        float2 f1 = __half22float2(hp[1]); \
        float2 f2 = __half22float2(hp[2]); \
        float2 f3 = __half22float2(hp[3]); \
        a[0] = fmaf(f0.x, (cc), a[0]); a[1] = fmaf(f0.y, (cc), a[1]); \
        a[2] = fmaf(f1.x, (cc), a[2]); a[3] = fmaf(f1.y, (cc), a[3]); \
        a[4] = fmaf(f2.x, (cc), a[4]); a[5] = fmaf(f2.y, (cc), a[5]); \
        a[6] = fmaf(f3.x, (cc), a[6]); a[7] = fmaf(f3.y, (cc), a[7]); }

    if (deg <= 16) {
        #pragma unroll
        for (int q = 0; q < 4; q++) {
            int e = q * 4 + g;
            int idx = min(e, deg - 1);
            int s = ssc[idx];
            float c = (e < deg) ? exc[idx] : 0.f;
            if (act) {
                float4 v = __ldg(&h4[s * LROW + l8]);
                ACC8(v, c)
            }
        }
    } else if (fits) {
        for (int it = 0; it < deg; it += 8) {
            int e0 = it + g, e1 = it + 4 + g;
            int i0 = min(e0, deg - 1), i1 = min(e1, deg - 1);
            int s0 = ssc[i0], s1 = ssc[i1];
            float c0 = (e0 < deg) ? exc[i0] : 0.f;
            float c1 = (e1 < deg) ? exc[i1] : 0.f;
            if (act) {
                float4 v0 = __ldg(&h4[s0 * LROW + l8]);
                float4 v1 = __ldg(&h4[s1 * LROW + l8]);
                ACC8(v0, c0)
                ACC8(v1, c1)
            }
        }
    } else {
        for (int it = 0; it < deg; it += 4) {
            int e = it + g;
            if (e < deg) {
                int s = srcs[beg + e];
                float ev = as_[s] + advv;
                ev = (ev > 0.f) ? ev : 0.2f * ev;
                float c = __expf(ev);
                if (act) {
                    float4 v = __ldg(&h4[s * LROW + l8]);
                    ACC8(v, c)
                }
            }
        }
    }
    #undef ACC8

    #pragma unroll
    for (int m = 8; m < 32; m <<= 1)
        #pragma unroll
        for (int j = 0; j < 8; j++)
            a[j] += __shfl_xor_sync(0xffffffffu, a[j], m);
    #pragma unroll
    for (int j = 0; j < 8; j++) a[j] *= rden;

    if (!FINAL) {
        if (lane < LROW) {
            float o[8];
            #pragma unroll
            for (int j = 0; j < 8; j++)
                o[j] = fmaxf(a[j] + bias[l8 * 8 + j], 0.f);
            float* dstp = outp + (size_t)d * F + l8 * 8;
            *(float4*)dstp       = make_float4(o[0], o[1], o[2], o[3]);
            *(float4*)(dstp + 4) = make_float4(o[4], o[5], o[6], o[7]);
        }
    } else {
        float v[8];
        float mx = __int_as_float(0xff800000);
        if (act) {
            #pragma unroll
            for (int j = 0; j < 8; j++) {
                v[j] = a[j] + bias[l8 * 8 + j];
                mx = fmaxf(mx, v[j]);
            }
        }
        #pragma unroll
        for (int m = 1; m < 8; m <<= 1) mx = fmaxf(mx, __shfl_xor_sync(0xffffffffu, mx, m));
        float se = 0.f;
        if (act) {
            #pragma unroll
            for (int j = 0; j < 8; j++) se += __expf(v[j] - mx);
        }
        #pragma unroll
        for (int m = 1; m < 8; m <<= 1) se += __shfl_xor_sync(0xffffffffu, se, m);
        float ls = mx + __logf(se);
        if (lane < LROW) {
            float* dstp = outp + (size_t)d * F + l8 * 8;
            *(float4*)dstp       = make_float4(v[0] - ls, v[1] - ls, v[2] - ls, v[3] - ls);
            *(float4*)(dstp + 4) = make_float4(v[4] - ls, v[5] - ls, v[6] - ls, v[7] - ls);
        }
    }
}

// ---------------------------------------------------------------------------
// Launch.  Side stream: memset(cnt), memset(bar), hist(1), scan(2), fill(3).
// Main: gemm1(4) -> agg1(5) -> gemm2(6) -> agg2(7).
// ---------------------------------------------------------------------------
extern "C" void kernel_launch(void* const* d_in, const int* in_sizes, int n_in,
                              void* d_out, int out_size) {
    const float* x       = (const float*)d_in[0];
    const unsigned int* ei_raw = (const unsigned int*)d_in[1];
    const float* W1      = (const float*)d_in[2];
    const float* a_src1  = (const float*)d_in[3];
    const float* a_dst1  = (const float*)d_in[4];
    const float* b1      = (const float*)d_in[5];
    const float* W2      = (const float*)d_in[6];
    const float* a_src2  = (const float*)d_in[7];
    const float* a_dst2  = (const float*)d_in[8];
    const float* b2      = (const float*)d_in[9];
    float* out           = (float*)d_out;

    int Nn = in_sizes[0] / 128;
    long long E = in_sizes[1] / 2;
    long long T = E + Nn;

    float *p_h1r, *p_as, *p_ad;
    __half *p_h1h, *p_h2h;
    int *p_cnt, *p_off, *p_srcs, *p_rank, *p_part, *p_bar;
    cudaGetSymbolAddress((void**)&p_h1h, g_h1h);
    cudaGetSymbolAddress((void**)&p_h1r, g_h1r);
    cudaGetSymbolAddress((void**)&p_h2h, g_h2h);
    cudaGetSymbolAddress((void**)&p_as, g_as);
    cudaGetSymbolAddress((void**)&p_ad, g_ad);
    cudaGetSymbolAddress((void**)&p_cnt, g_cnt);
    cudaGetSymbolAddress((void**)&p_off, g_off);
    cudaGetSymbolAddress((void**)&p_srcs, g_srcs);
    cudaGetSymbolAddress((void**)&p_rank, g_rank);
    cudaGetSymbolAddress((void**)&p_part, g_partials);
    cudaGetSymbolAddress((void**)&p_bar, g_barrier);

    static cudaStream_t s2 = nullptr;
    static cudaEvent_t evF = nullptr, evC = nullptr;
    if (!s2) {
        cudaStreamCreateWithFlags(&s2, cudaStreamNonBlocking);
        cudaEventCreateWithFlags(&evF, cudaEventDisableTiming);
        cudaEventCreateWithFlags(&evC, cudaEventDisableTiming);
    }

    const int TB = 256;
    int nb = (Nn + 1023) / 1024;                 // 98
    long long E4 = (E + 3) / 4;

    // ---- Fork: CSR build on s2, gemm1 on main stream ----
    cudaEventRecord(evF, 0);
    cudaStreamWaitEvent(s2, evF, 0);

    cudaMemsetAsync(p_cnt, 0, (size_t)Nn * sizeof(int), s2);
    cudaMemsetAsync(p_bar, 0, sizeof(int), s2);
    hist_kernel<<<(int)((E4 + TB - 1) / TB), TB, 0, s2>>>(ei_raw, p_cnt, p_rank, E);
    scan_kernel<<<nb, 1024, 0, s2>>>(p_cnt, p_off, p_srcs, p_part, p_bar, Nn, (int)T);
    fill_kernel<<<(int)((E4 + TB - 1) / TB), TB, 0, s2>>>(ei_raw, p_off, p_rank, p_srcs, E);
    cudaEventRecord(evC, s2);

    gemm1_kernel<<<(Nn + 127) / 128, 128>>>(x, W1, a_src1, a_dst1, p_h1h, p_as, p_ad, Nn);

    // ---- Join ----
    cudaStreamWaitEvent(0, evC, 0);
    gat_agg_kernel<64, false><<<(Nn + 7) / 8, 256>>>(p_srcs, p_off, p_as, p_ad, p_h1h, b1, p_h1r, Nn);
    gemm2_kernel<<<(Nn + 31) / 32, 128>>>(p_h1r, W2, a_src2, a_dst2, p_h2h, p_as, p_ad, Nn);
    gat_agg_kernel<40, true><<<(Nn + 7) / 8, 256>>>(p_srcs, p_off, p_as, p_ad, p_h2h, b2, out, Nn);
}

// round 17
// speedup vs baseline: 1.1698x; 1.1698x over previous
#include <cuda_runtime.h>
#include <cuda_fp16.h>
#include <math.h>

// ---------------------------------------------------------------------------
// N=100000, F_in=128, F_hid=64, F_out=40, E=1600000 (+N self loops).
// h1 / h2 stored fp16. gemm1 uses HMMA tensor cores (fp16 in, fp32 acc).
// ---------------------------------------------------------------------------
#define MAXN 100000
#define MAXE 1700096

__device__ __half g_h1h[(size_t)MAXN * 64];
__device__ float  g_h1r[(size_t)MAXN * 64];
__device__ __half g_h2h[(size_t)MAXN * 40];
__device__ float  g_as[MAXN];
__device__ float  g_ad[MAXN];
__device__ int    g_cnt[MAXN];
__device__ int    g_off[MAXN + 1];
__device__ int    g_srcs[MAXE];
__device__ int    g_rank[MAXE];
__device__ int    g_partials[128];
__device__ int    g_barrier;

static __device__ __forceinline__ int detect_is64(const unsigned int* w) {
    unsigned int any = 0;
    #pragma unroll
    for (int k = 0; k < 32; k++) any |= w[2 * k + 1];
    return any == 0u;
}

// ---------------------------------------------------------------------------
// Hist: 4 edges per thread; count destinations, record per-edge rank.
// ---------------------------------------------------------------------------
__global__ void hist_kernel(const unsigned int* __restrict__ w,
                            int* __restrict__ cnt, int* __restrict__ rank,
                            long long E) {
    __shared__ int sis64;
    if (threadIdx.x == 0) sis64 = detect_is64(w);
    __syncthreads();
    int is64 = sis64;

    long long i4 = ((long long)blockIdx.x * blockDim.x + threadIdx.x) * 4;
    if (i4 >= E) return;
    int nv = (int)((E - i4 < 4) ? (E - i4) : 4);

    int d[4];
    if (is64) {
        const uint2* w2 = (const uint2*)w;
        #pragma unroll
        for (int q = 0; q < 4; q++)
            if (q < nv) d[q] = (int)w2[E + i4 + q].x;
    } else {
        if (nv == 4 && (((E + i4) & 3) == 0)) {
            uint4 v = *(const uint4*)&w[E + i4];
            d[0] = (int)v.x; d[1] = (int)v.y; d[2] = (int)v.z; d[3] = (int)v.w;
        } else {
            #pragma unroll
            for (int q = 0; q < 4; q++)
                if (q < nv) d[q] = (int)w[E + i4 + q];
        }
    }
    int r[4];
    #pragma unroll
    for (int q = 0; q < 4; q++)
        if (q < nv) r[q] = atomicAdd(&cnt[d[q]], 1);
    if (nv == 4) *(int4*)&rank[i4] = make_int4(r[0], r[1], r[2], r[3]);
    else {
        #pragma unroll
        for (int q = 0; q < 4; q++)
            if (q < nv) rank[i4 + q] = r[q];
    }
}

// ---------------------------------------------------------------------------
// Scan (+ self-loop placement)
// ---------------------------------------------------------------------------
__global__ void scan_kernel(const int* __restrict__ cnt,
                            int* __restrict__ off, int* __restrict__ srcs,
                            int* __restrict__ partials, int* __restrict__ barrier,
                            int n, int total) {
    __shared__ int sm[1024];
    __shared__ int pf[128];
    int tid = threadIdx.x, b = blockIdx.x;
    int i = b * 1024 + tid;
    int cv = (i < n) ? cnt[i] : 0;
    int v = (i < n) ? cv + 1 : 0;
    sm[tid] = v;
    __syncthreads();
    #pragma unroll
    for (int o = 1; o < 1024; o <<= 1) {
        int t = (tid >= o) ? sm[tid - o] : 0;
        __syncthreads();
        sm[tid] += t;
        __syncthreads();
    }
    int incl = sm[tid];

    if (tid == 0) {
        partials[b] = sm[1023];
        __threadfence();
        atomicAdd(barrier, 1);
        while (atomicAdd(barrier, 0) < gridDim.x) {}
    }
    __syncthreads();

    pf[tid & 127] = 0;
    __syncthreads();
    if (tid < 128) pf[tid] = (tid < b) ? partials[tid] : 0;
    __syncthreads();
    #pragma unroll
    for (int o = 64; o; o >>= 1) {
        if (tid < o) pf[tid] += pf[tid + o];
        __syncthreads();
    }
    int prefix = pf[0];

    if (i < n) {
        int o = prefix + incl - v;
        off[i] = o;
        srcs[o + cv] = i;
    }
    if (i == 0) off[n] = total;
}

// ---------------------------------------------------------------------------
// Fill: 4 edges per thread, atomic-free scatter via precomputed ranks.
// ---------------------------------------------------------------------------
__global__ void fill_kernel(const unsigned int* __restrict__ w,
                            const int* __restrict__ off,
                            const int* __restrict__ rank,
                            int* __restrict__ srcs, long long E) {
    __shared__ int sis64;
    if (threadIdx.x == 0) sis64 = detect_is64(w);
    __syncthreads();
    int is64 = sis64;

    long long i4 = ((long long)blockIdx.x * blockDim.x + threadIdx.x) * 4;
    if (i4 >= E) return;
    int nv = (int)((E - i4 < 4) ? (E - i4) : 4);

    int s[4], d[4];
    if (is64) {
        const uint2* w2 = (const uint2*)w;
        #pragma unroll
        for (int q = 0; q < 4; q++)
            if (q < nv) { s[q] = (int)w2[i4 + q].x; d[q] = (int)w2[E + i4 + q].x; }
    } else {
        if (nv == 4 && (((E + i4) & 3) == 0)) {
            uint4 vs = *(const uint4*)&w[i4];
            uint4 vd = *(const uint4*)&w[E + i4];
            s[0] = (int)vs.x; s[1] = (int)vs.y; s[2] = (int)vs.z; s[3] = (int)vs.w;
            d[0] = (int)vd.x; d[1] = (int)vd.y; d[2] = (int)vd.z; d[3] = (int)vd.w;
        } else {
            #pragma unroll
            for (int q = 0; q < 4; q++)
                if (q < nv) { s[q] = (int)w[i4 + q]; d[q] = (int)w[E + i4 + q]; }
        }
    }
    int r[4];
    if (nv == 4) { int4 rv = *(const int4*)&rank[i4]; r[0]=rv.x; r[1]=rv.y; r[2]=rv.z; r[3]=rv.w; }
    else {
        #pragma unroll
        for (int q = 0; q < 4; q++)
            if (q < nv) r[q] = rank[i4 + q];
    }
    #pragma unroll
    for (int q = 0; q < 4; q++)
        if (q < nv) srcs[off[d[q]] + r[q]] = s[q];
}

// ---------------------------------------------------------------------------
// GEMM1 (tensor cores): h = x @ W, fp16 inputs, fp32 accum, fp16 output.
// Block: 256 threads / 8 warps, tile 128 rows x 64 cols, K chunked 2x64.
// Warp wr handles rows wr*16..+15 via mma.sync m16n8k16 (8 n-tiles, 4 k-steps
// per chunk). Alpha dots computed from fp32 C frags, quad-reduced.
// ---------------------------------------------------------------------------
__global__ void gemm1_kernel(const float* __restrict__ x,
                             const float* __restrict__ W,
                             const float* __restrict__ asv,
                             const float* __restrict__ adv,
                             __half* __restrict__ h,
                             float* __restrict__ as_, float* __restrict__ ad_,
                             int Nn) {
    __shared__ __half Xs[128 * 72];   // 128 rows x (64 + 8 pad)
    __shared__ __half Wt[64 * 72];    // 64 n x (64 + 8 pad), k-major
    int tid = threadIdx.x;
    int lane = tid & 31;
    int wr = tid >> 5;                // warp 0..7
    int g = lane >> 2;                // group 0..7
    int tig = lane & 3;               // thread-in-group

    int row0 = blockIdx.x * 128;

    float c[8][4];
    #pragma unroll
    for (int nt = 0; nt < 8; nt++)
        #pragma unroll
        for (int j = 0; j < 4; j++) c[nt][j] = 0.f;

    const float4* x4 = (const float4*)x;

    for (int kc = 0; kc < 2; kc++) {
        // Load X chunk: 128 rows x 64 k as fp16 (pad 8)
        #pragma unroll
        for (int i = tid; i < 128 * 16; i += 256) {
            int row = i >> 4;
            int c4  = i & 15;
            int gr = row0 + row;
            float4 v = (gr < Nn) ? x4[(size_t)gr * 32 + kc * 16 + c4]
                                 : make_float4(0.f, 0.f, 0.f, 0.f);
            __half2 p0 = __floats2half2_rn(v.x, v.y);
            __half2 p1 = __floats2half2_rn(v.z, v.w);
            uint2 pk;
            pk.x = *(unsigned int*)&p0;
            pk.y = *(unsigned int*)&p1;
            *(uint2*)&Xs[row * 72 + c4 * 4] = pk;
        }
        // Load W chunk transposed: Wt[n][k] fp16
        #pragma unroll
        for (int i = tid; i < 4096; i += 256) {
            int k = i >> 6;
            int n = i & 63;
            Wt[n * 72 + k] = __float2half_rn(W[(kc * 64 + k) * 64 + n]);
        }
        __syncthreads();

        #pragma unroll
        for (int kk = 0; kk < 4; kk++) {
            int ak = kk * 16 + tig * 2;
            unsigned int a0 = *(const unsigned int*)&Xs[(wr * 16 + g) * 72 + ak];
            unsigned int a1 = *(const unsigned int*)&Xs[(wr * 16 + g + 8) * 72 + ak];
            unsigned int a2 = *(const unsigned int*)&Xs[(wr * 16 + g) * 72 + ak + 8];
            unsigned int a3 = *(const unsigned int*)&Xs[(wr * 16 + g + 8) * 72 + ak + 8];
            #pragma unroll
            for (int nt = 0; nt < 8; nt++) {
                unsigned int b0 = *(const unsigned int*)&Wt[(nt * 8 + g) * 72 + ak];
                unsigned int b1 = *(const unsigned int*)&Wt[(nt * 8 + g) * 72 + ak + 8];
                asm volatile(
                    "mma.sync.aligned.m16n8k16.row.col.f32.f16.f16.f32 "
                    "{%0,%1,%2,%3}, {%4,%5,%6,%7}, {%8,%9}, {%0,%1,%2,%3};"
                    : "+f"(c[nt][0]), "+f"(c[nt][1]), "+f"(c[nt][2]), "+f"(c[nt][3])
                    : "r"(a0), "r"(a1), "r"(a2), "r"(a3), "r"(b0), "r"(b1));
            }
        }
        __syncthreads();
    }

    // Epilogue: alpha dots + fp16 h stores.
    int r0 = row0 + wr * 16 + g;
    int r1 = r0 + 8;
    float ps0 = 0.f, pd0 = 0.f, ps1 = 0.f, pd1 = 0.f;
    #pragma unroll
    for (int nt = 0; nt < 8; nt++) {
        int col = nt * 8 + tig * 2;
        float sa0 = asv[col], sa1 = asv[col + 1];
        float da0 = adv[col], da1 = adv[col + 1];
        ps0 += c[nt][0] * sa0 + c[nt][1] * sa1;
        pd0 += c[nt][0] * da0 + c[nt][1] * da1;
        ps1 += c[nt][2] * sa0 + c[nt][3] * sa1;
        pd1 += c[nt][2] * da0 + c[nt][3] * da1;
    }
    #pragma unroll
    for (int m = 1; m < 4; m <<= 1) {
        ps0 += __shfl_xor_sync(0xffffffffu, ps0, m);
        pd0 += __shfl_xor_sync(0xffffffffu, pd0, m);
        ps1 += __shfl_xor_sync(0xffffffffu, ps1, m);
        pd1 += __shfl_xor_sync(0xffffffffu, pd1, m);
    }
    if (tig == 0) {
        if (r0 < Nn) { as_[r0] = ps0; ad_[r0] = pd0; }
        if (r1 < Nn) { as_[r1] = ps1; ad_[r1] = pd1; }
    }
    #pragma unroll
    for (int nt = 0; nt < 8; nt++) {
        int col = nt * 8 + tig * 2;
        if (r0 < Nn) {
            __half2 p = __floats2half2_rn(c[nt][0], c[nt][1]);
            *(__half2*)(h + (size_t)r0 * 64 + col) = p;
        }
        if (r1 < Nn) {
            __half2 p = __floats2half2_rn(c[nt][2], c[nt][3]);
            *(__half2*)(h + (size_t)r1 * 64 + col) = p;
        }
    }
}

// ---------------------------------------------------------------------------
// GEMM2: h2 = h1r @ W2 (K=64, C=40), fp16 output, alpha dots fused.
// ---------------------------------------------------------------------------
__global__ void gemm2_kernel(const float* __restrict__ x,
                             const float* __restrict__ W,
                             const float* __restrict__ asv,
                             const float* __restrict__ adv,
                             __half* __restrict__ h,
                             float* __restrict__ as_, float* __restrict__ ad_,
                             int Nn) {
    __shared__ float Xs[32][64];
    __shared__ float Ws[64][40];
    int tid = threadIdx.x;
    int row0 = blockIdx.x * 32;

    #pragma unroll
    for (int i = tid; i < 64 * 40; i += 128) Ws[i / 40][i % 40] = W[i];

    const float4* x4 = (const float4*)x;
    float4* Xs4 = (float4*)Xs;
    #pragma unroll
    for (int i = tid; i < 32 * 16; i += 128) {
        long long gi = (long long)row0 * 16 + i;
        Xs4[i] = (gi < (long long)Nn * 16) ? x4[gi] : make_float4(0.f, 0.f, 0.f, 0.f);
    }
    __syncthreads();

    int r0 = (tid >> 3) * 2;
    int c0 = (tid & 7) * 5;
    float acc[2][5] = {};
    #pragma unroll 4
    for (int k = 0; k < 64; k++) {
        float xv0 = Xs[r0][k];
        float xv1 = Xs[r0 + 1][k];
        #pragma unroll
        for (int j = 0; j < 5; j++) {
            float wv = Ws[k][c0 + j];
            acc[0][j] += xv0 * wv;
            acc[1][j] += xv1 * wv;
        }
    }

    float sa[5], da[5];
    #pragma unroll
    for (int j = 0; j < 5; j++) { sa[j] = asv[c0 + j]; da[j] = adv[c0 + j]; }

    #pragma unroll
    for (int i = 0; i < 2; i++) {
        int row = row0 + r0 + i;
        float ps = 0.f, pd = 0.f;
        #pragma unroll
        for (int j = 0; j < 5; j++) {
            ps += acc[i][j] * sa[j];
            pd += acc[i][j] * da[j];
        }
        #pragma unroll
        for (int m = 1; m < 8; m <<= 1) {
            ps += __shfl_xor_sync(0xffffffffu, ps, m);
            pd += __shfl_xor_sync(0xffffffffu, pd, m);
        }
        if (row < Nn) {
            __half* dstp = h + (size_t)row * 40 + c0;
            #pragma unroll
            for (int j = 0; j < 5; j++) dstp[j] = __float2half_rn(acc[i][j]);
            if ((tid & 7) == 0) { as_[row] = ps; ad_[row] = pd; }
        }
    }
}

// ---------------------------------------------------------------------------
// Fused GAT aggregation (round-15 best): warp per dst, fp16 rows, deg<=16
// fast path, 8-edge chunks otherwise, rden post-combine.
// ---------------------------------------------------------------------------
template <int F, bool FINAL>
__global__ void gat_agg_kernel(const int* __restrict__ srcs,
                               const int* __restrict__ off,
                               const float* __restrict__ as_,
                               const float* __restrict__ ad_,
                               const __half* __restrict__ h,
                               const float* __restrict__ bias,
                               float* __restrict__ outp, int Nn) {
    constexpr int LROW = F / 8;
    __shared__ float exco[8][96];
    __shared__ int   sso[8][96];
    int w = threadIdx.x >> 5, lane = threadIdx.x & 31;
    int d = blockIdx.x * 8 + w;
    if (d >= Nn) return;
    int beg = off[d], end = off[d + 1];
    int deg = end - beg;
    float advv = ad_[d];
    float* exc = exco[w];
    int*   ssc = sso[w];
    bool fits = (deg <= 96);

    float sum = 0.f;
    for (int i = lane; i < deg; i += 32) {
        int s = srcs[beg + i];
        float e = as_[s] + advv;
        e = (e > 0.f) ? e : 0.2f * e;
        float xv = __expf(e);
        if (fits) { exc[i] = xv; ssc[i] = s; }
        sum += xv;
    }
    #pragma unroll
    for (int m = 16; m; m >>= 1) sum += __shfl_xor_sync(0xffffffffu, sum, m);
    float rden = 1.0f / sum;
    __syncwarp();

    int g = lane >> 3, l8 = lane & 7;
    const bool act = (F == 64) || (l8 < LROW);
    float a[8] = {0.f, 0.f, 0.f, 0.f, 0.f, 0.f, 0.f, 0.f};
    const float4* h4 = (const float4*)h;

    #define ACC8(vv, cc) { \
        const __half2* hp = (const __half2*)&(vv); \
        float2 f0 = __half22float2(hp[0]); \
        float2 f1 = __half22float2(hp[1]); \
        float2 f2 = __half22float2(hp[2]); \
        float2 f3 = __half22float2(hp[3]); \
        a[0] = fmaf(f0.x, (cc), a[0]); a[1] = fmaf(f0.y, (cc), a[1]); \
        a[2] = fmaf(f1.x, (cc), a[2]); a[3] = fmaf(f1.y, (cc), a[3]); \
        a[4] = fmaf(f2.x, (cc), a[4]); a[5] = fmaf(f2.y, (cc), a[5]); \
        a[6] = fmaf(f3.x, (cc), a[6]); a[7] = fmaf(f3.y, (cc), a[7]); }

    if (deg <= 16) {
        #pragma unroll
        for (int q = 0; q < 4; q++) {
            int e = q * 4 + g;
            int idx = min(e, deg - 1);
            int s = ssc[idx];
            float c = (e < deg) ? exc[idx] : 0.f;
            if (act) {
                float4 v = __ldg(&h4[s * LROW + l8]);
                ACC8(v, c)
            }
        }
    } else if (fits) {
        for (int it = 0; it < deg; it += 8) {
            int e0 = it + g, e1 = it + 4 + g;
            int i0 = min(e0, deg - 1), i1 = min(e1, deg - 1);
            int s0 = ssc[i0], s1 = ssc[i1];
            float c0 = (e0 < deg) ? exc[i0] : 0.f;
            float c1 = (e1 < deg) ? exc[i1] : 0.f;
            if (act) {
                float4 v0 = __ldg(&h4[s0 * LROW + l8]);
                float4 v1 = __ldg(&h4[s1 * LROW + l8]);
                ACC8(v0, c0)
                ACC8(v1, c1)
            }
        }
    } else {
        for (int it = 0; it < deg; it += 4) {
            int e = it + g;
            if (e < deg) {
                int s = srcs[beg + e];
                float ev = as_[s] + advv;
                ev = (ev > 0.f) ? ev : 0.2f * ev;
                float c = __expf(ev);
                if (act) {
                    float4 v = __ldg(&h4[s * LROW + l8]);
                    ACC8(v, c)
                }
            }
        }
    }
    #undef ACC8

    #pragma unroll
    for (int m = 8; m < 32; m <<= 1)
        #pragma unroll
        for (int j = 0; j < 8; j++)
            a[j] += __shfl_xor_sync(0xffffffffu, a[j], m);
    #pragma unroll
    for (int j = 0; j < 8; j++) a[j] *= rden;

    if (!FINAL) {
        if (lane < LROW) {
            float o[8];
            #pragma unroll
            for (int j = 0; j < 8; j++)
                o[j] = fmaxf(a[j] + bias[l8 * 8 + j], 0.f);
            float* dstp = outp + (size_t)d * F + l8 * 8;
            *(float4*)dstp       = make_float4(o[0], o[1], o[2], o[3]);
            *(float4*)(dstp + 4) = make_float4(o[4], o[5], o[6], o[7]);
        }
    } else {
        float v[8];
        float mx = __int_as_float(0xff800000);
        if (act) {
            #pragma unroll
            for (int j = 0; j < 8; j++) {
                v[j] = a[j] + bias[l8 * 8 + j];
                mx = fmaxf(mx, v[j]);
            }
        }
        #pragma unroll
        for (int m = 1; m < 8; m <<= 1) mx = fmaxf(mx, __shfl_xor_sync(0xffffffffu, mx, m));
        float se = 0.f;
        if (act) {
            #pragma unroll
            for (int j = 0; j < 8; j++) se += __expf(v[j] - mx);
        }
        #pragma unroll
        for (int m = 1; m < 8; m <<= 1) se += __shfl_xor_sync(0xffffffffu, se, m);
        float ls = mx + __logf(se);
        if (lane < LROW) {
            float* dstp = outp + (size_t)d * F + l8 * 8;
            *(float4*)dstp       = make_float4(v[0] - ls, v[1] - ls, v[2] - ls, v[3] - ls);
            *(float4*)(dstp + 4) = make_float4(v[4] - ls, v[5] - ls, v[6] - ls, v[7] - ls);
        }
    }
}

// ---------------------------------------------------------------------------
// Launch.  Side stream: memset(cnt), memset(bar), hist, scan, fill.
// Main: gemm1 (tensor) -> agg1 -> gemm2 -> agg2.
// ---------------------------------------------------------------------------
extern "C" void kernel_launch(void* const* d_in, const int* in_sizes, int n_in,
                              void* d_out, int out_size) {
    const float* x       = (const float*)d_in[0];
    const unsigned int* ei_raw = (const unsigned int*)d_in[1];
    const float* W1      = (const float*)d_in[2];
    const float* a_src1  = (const float*)d_in[3];
    const float* a_dst1  = (const float*)d_in[4];
    const float* b1      = (const float*)d_in[5];
    const float* W2      = (const float*)d_in[6];
    const float* a_src2  = (const float*)d_in[7];
    const float* a_dst2  = (const float*)d_in[8];
    const float* b2      = (const float*)d_in[9];
    float* out           = (float*)d_out;

    int Nn = in_sizes[0] / 128;
    long long E = in_sizes[1] / 2;
    long long T = E + Nn;

    float *p_h1r, *p_as, *p_ad;
    __half *p_h1h, *p_h2h;
    int *p_cnt, *p_off, *p_srcs, *p_rank, *p_part, *p_bar;
    cudaGetSymbolAddress((void**)&p_h1h, g_h1h);
    cudaGetSymbolAddress((void**)&p_h1r, g_h1r);
    cudaGetSymbolAddress((void**)&p_h2h, g_h2h);
    cudaGetSymbolAddress((void**)&p_as, g_as);
    cudaGetSymbolAddress((void**)&p_ad, g_ad);
    cudaGetSymbolAddress((void**)&p_cnt, g_cnt);
    cudaGetSymbolAddress((void**)&p_off, g_off);
    cudaGetSymbolAddress((void**)&p_srcs, g_srcs);
    cudaGetSymbolAddress((void**)&p_rank, g_rank);
    cudaGetSymbolAddress((void**)&p_part, g_partials);
    cudaGetSymbolAddress((void**)&p_bar, g_barrier);

    static cudaStream_t s2 = nullptr;
    static cudaEvent_t evF = nullptr, evC = nullptr;
    if (!s2) {
        cudaStreamCreateWithFlags(&s2, cudaStreamNonBlocking);
        cudaEventCreateWithFlags(&evF, cudaEventDisableTiming);
        cudaEventCreateWithFlags(&evC, cudaEventDisableTiming);
    }

    const int TB = 256;
    int nb = (Nn + 1023) / 1024;                 // 98
    long long E4 = (E + 3) / 4;

    // ---- Fork: CSR build on s2, gemm1 on main stream ----
    cudaEventRecord(evF, 0);
    cudaStreamWaitEvent(s2, evF, 0);

    cudaMemsetAsync(p_cnt, 0, (size_t)Nn * sizeof(int), s2);
    cudaMemsetAsync(p_bar, 0, sizeof(int), s2);
    hist_kernel<<<(int)((E4 + TB - 1) / TB), TB, 0, s2>>>(ei_raw, p_cnt, p_rank, E);
    scan_kernel<<<nb, 1024, 0, s2>>>(p_cnt, p_off, p_srcs, p_part, p_bar, Nn, (int)T);
    fill_kernel<<<(int)((E4 + TB - 1) / TB), TB, 0, s2>>>(ei_raw, p_off, p_rank, p_srcs, E);
    cudaEventRecord(evC, s2);

    gemm1_kernel<<<(Nn + 127) / 128, 256>>>(x, W1, a_src1, a_dst1, p_h1h, p_as, p_ad, Nn);

    // ---- Join ----
    cudaStreamWaitEvent(0, evC, 0);
    gat_agg_kernel<64, false><<<(Nn + 7) / 8, 256>>>(p_srcs, p_off, p_as, p_ad, p_h1h, b1, p_h1r, Nn);
    gemm2_kernel<<<(Nn + 31) / 32, 128>>>(p_h1r, W2, a_src2, a_dst2, p_h2h, p_as, p_ad, Nn);
    gat_agg_kernel<40, true><<<(Nn + 7) / 8, 256>>>(p_srcs, p_off, p_as, p_ad, p_h2h, b2, out, Nn);
}